// round 12
// baseline (speedup 1.0000x reference)
#include <cuda_runtime.h>

#define NNET   722
#define CAMD   10
#define HD     10
#define LODD   6

#define NT     8       // networks per block; lane&7 -> network (4-way LDS broadcast)
#define WS     388     // floats per network; 388%32==4 -> 8 distinct 16B bank-slots; 16B-aligned
#define BT     4       // batch elements per thread
#define ITERS  8
#define BTILE  1024    // 8 warps * 4 groups * BT * ITERS

// padded smem layout per network (stride WS):
//   [0,132)    W1: 11 rows x 12 (10 used)
//   [132,144)  b1 (10 used)
//   [144,264)  W2: 10 rows x 12 (10 used)
//   [264,276)  b2 (10 used)
//   [276,356)  W3: 10 rows x 8 (6 used)
//   [356,364)  b3 (6 used)
#define OW1 0
#define OB1 132
#define OW2 144
#define OB2 264
#define OW3 276
#define OB3 356

typedef unsigned long long u64;

__device__ __forceinline__ u64 fma2(u64 a, u64 b, u64 c) {
    u64 d;
    asm("fma.rn.f32x2 %0, %1, %2, %3;" : "=l"(d) : "l"(a), "l"(b), "l"(c));
    return d;
}
__device__ __forceinline__ u64 bcast2(float x) {      // {x, x}
    u64 d;
    asm("mov.b64 %0, {%1, %1};" : "=l"(d) : "f"(x));
    return d;
}
__device__ __forceinline__ void unpack2(u64 v, float& lo, float& hi) {
    asm("mov.b64 {%0, %1}, %2;" : "=f"(lo), "=f"(hi) : "l"(v));
}
__device__ __forceinline__ u64 lds64(const float* p) {            // 1 pair
    return *reinterpret_cast<const u64*>(p);
}
__device__ __forceinline__ ulonglong2 lds128(const float* p) {    // 2 pairs
    return *reinterpret_cast<const ulonglong2*>(p);
}

__global__ __launch_bounds__(256, 2)
void grouped_mlp_kernel(const float* __restrict__ prior,
                        const float* __restrict__ camera,
                        const float* __restrict__ W1, const float* __restrict__ b1,
                        const float* __restrict__ W2, const float* __restrict__ b2,
                        const float* __restrict__ W3, const float* __restrict__ b3,
                        float* __restrict__ out)
{
    __shared__ __align__(16) float ws[NT * WS];

    const int tid    = threadIdx.x;
    const int n0     = blockIdx.x * NT;
    const int b_base = blockIdx.y * BTILE;

    // ---- cooperative weight staging into the padded layout ----
    for (int f = tid; f < NT * 110; f += 256) {
        int nl = f / 110, idx = f - nl * 110, i = idx / 10, c = idx - i * 10;
        if (n0 + nl < NNET) ws[nl * WS + OW1 + i * 12 + c] = W1[(n0 + nl) * 110 + idx];
    }
    for (int f = tid; f < NT * 10; f += 256) {
        int nl = f / 10, idx = f - nl * 10;
        if (n0 + nl < NNET) ws[nl * WS + OB1 + idx] = b1[(n0 + nl) * 10 + idx];
    }
    for (int f = tid; f < NT * 100; f += 256) {
        int nl = f / 100, idx = f - nl * 100, i = idx / 10, c = idx - i * 10;
        if (n0 + nl < NNET) ws[nl * WS + OW2 + i * 12 + c] = W2[(n0 + nl) * 100 + idx];
    }
    for (int f = tid; f < NT * 10; f += 256) {
        int nl = f / 10, idx = f - nl * 10;
        if (n0 + nl < NNET) ws[nl * WS + OB2 + idx] = b2[(n0 + nl) * 10 + idx];
    }
    for (int f = tid; f < NT * 60; f += 256) {
        int nl = f / 60, idx = f - nl * 60, h = idx / 6, c = idx - h * 6;
        if (n0 + nl < NNET) ws[nl * WS + OW3 + h * 8 + c] = W3[(n0 + nl) * 60 + idx];
    }
    for (int f = tid; f < NT * 6; f += 256) {
        int nl = f / 6, idx = f - nl * 6;
        if (n0 + nl < NNET) ws[nl * WS + OB3 + idx] = b3[(n0 + nl) * 6 + idx];
    }
    __syncthreads();

    const int nl = tid & 7;             // network (lanes nl, nl+8, nl+16, nl+24 share)
    const int g  = (tid >> 3) & 3;      // batch subgroup within warp
    const int wp = tid >> 5;            // warp id
    const int n  = n0 + nl;
    const float* __restrict__ w = &ws[nl * WS];

    if (n >= NNET) return;              // tail tile; no barriers below

    #pragma unroll 1
    for (int it = 0; it < ITERS; ++it) {
        const int b0 = b_base + it * 128 + wp * 16 + g * BT;

        // ---------------- layer 1: 11 -> 10 (h-pairs packed) ----------------
        u64 acc[BT][HD / 2];
        {   // feature 0 = prior (4 x 32B rows per warp, coalesced), bias folded
            const ulonglong2 wa = lds128(&w[OW1]);
            const ulonglong2 wb = lds128(&w[OW1 + 4]);
            const u64        wc = lds64 (&w[OW1 + 8]);
            const ulonglong2 ba = lds128(&w[OB1]);
            const ulonglong2 bb = lds128(&w[OB1 + 4]);
            const u64        bc = lds64 (&w[OB1 + 8]);
            #pragma unroll
            for (int t = 0; t < BT; ++t) {
                const u64 xp = bcast2(prior[(size_t)(b0 + t) * NNET + n]);
                acc[t][0] = fma2(xp, wa.x, ba.x);
                acc[t][1] = fma2(xp, wa.y, ba.y);
                acc[t][2] = fma2(xp, wb.x, bb.x);
                acc[t][3] = fma2(xp, wb.y, bb.y);
                acc[t][4] = fma2(xp, wc,   bc);
            }
        }
        #pragma unroll
        for (int m = 0; m < 5; ++m) {   // camera features in pairs (float2 LDG)
            float2 cv[BT];
            #pragma unroll
            for (int t = 0; t < BT; ++t)
                cv[t] = __ldg(reinterpret_cast<const float2*>(
                              camera + (size_t)(b0 + t) * CAMD + 2 * m));
            #pragma unroll
            for (int s = 0; s < 2; ++s) {
                const int base = OW1 + (2 * m + 1 + s) * 12;
                const ulonglong2 wa = lds128(&w[base]);
                const ulonglong2 wb = lds128(&w[base + 4]);
                const u64        wc = lds64 (&w[base + 8]);
                #pragma unroll
                for (int t = 0; t < BT; ++t) {
                    const u64 xp = bcast2(s ? cv[t].y : cv[t].x);
                    acc[t][0] = fma2(xp, wa.x, acc[t][0]);
                    acc[t][1] = fma2(xp, wa.y, acc[t][1]);
                    acc[t][2] = fma2(xp, wb.x, acc[t][2]);
                    acc[t][3] = fma2(xp, wb.y, acc[t][3]);
                    acc[t][4] = fma2(xp, wc,   acc[t][4]);
                }
            }
        }
        // relu -> h1 scalars
        float h1[BT][HD];
        #pragma unroll
        for (int t = 0; t < BT; ++t)
            #pragma unroll
            for (int j = 0; j < HD / 2; ++j) {
                float lo, hi; unpack2(acc[t][j], lo, hi);
                h1[t][2 * j]     = fmaxf(lo, 0.0f);
                h1[t][2 * j + 1] = fmaxf(hi, 0.0f);
            }

        // ---------------- layer 2: 10 -> 10 (k-pairs packed) ----------------
        u64 acc2[BT][HD / 2];
        {   // h = 0, bias folded
            const ulonglong2 wa = lds128(&w[OW2]);
            const ulonglong2 wb = lds128(&w[OW2 + 4]);
            const u64        wc = lds64 (&w[OW2 + 8]);
            const ulonglong2 ba = lds128(&w[OB2]);
            const ulonglong2 bb = lds128(&w[OB2 + 4]);
            const u64        bc = lds64 (&w[OB2 + 8]);
            #pragma unroll
            for (int t = 0; t < BT; ++t) {
                const u64 xp = bcast2(h1[t][0]);
                acc2[t][0] = fma2(xp, wa.x, ba.x);
                acc2[t][1] = fma2(xp, wa.y, ba.y);
                acc2[t][2] = fma2(xp, wb.x, bb.x);
                acc2[t][3] = fma2(xp, wb.y, bb.y);
                acc2[t][4] = fma2(xp, wc,   bc);
            }
        }
        #pragma unroll
        for (int h = 1; h < HD; ++h) {
            const int base = OW2 + h * 12;
            const ulonglong2 wa = lds128(&w[base]);
            const ulonglong2 wb = lds128(&w[base + 4]);
            const u64        wc = lds64 (&w[base + 8]);
            #pragma unroll
            for (int t = 0; t < BT; ++t) {
                const u64 xp = bcast2(h1[t][h]);
                acc2[t][0] = fma2(xp, wa.x, acc2[t][0]);
                acc2[t][1] = fma2(xp, wa.y, acc2[t][1]);
                acc2[t][2] = fma2(xp, wb.x, acc2[t][2]);
                acc2[t][3] = fma2(xp, wb.y, acc2[t][3]);
                acc2[t][4] = fma2(xp, wc,   acc2[t][4]);
            }
        }
        // relu -> h2 scalars
        float h2[BT][HD];
        #pragma unroll
        for (int t = 0; t < BT; ++t)
            #pragma unroll
            for (int j = 0; j < HD / 2; ++j) {
                float lo, hi; unpack2(acc2[t][j], lo, hi);
                h2[t][2 * j]     = fmaxf(lo, 0.0f);
                h2[t][2 * j + 1] = fmaxf(hi, 0.0f);
            }

        // ---------------- layer 3: 10 -> 6 (o-pairs packed) ----------------
        u64 acc3[BT][LODD / 2];
        {   // h = 0, bias folded
            const ulonglong2 wa = lds128(&w[OW3]);
            const u64        wc = lds64 (&w[OW3 + 4]);
            const ulonglong2 ba = lds128(&w[OB3]);
            const u64        bc = lds64 (&w[OB3 + 4]);
            #pragma unroll
            for (int t = 0; t < BT; ++t) {
                const u64 xp = bcast2(h2[t][0]);
                acc3[t][0] = fma2(xp, wa.x, ba.x);
                acc3[t][1] = fma2(xp, wa.y, ba.y);
                acc3[t][2] = fma2(xp, wc,   bc);
            }
        }
        #pragma unroll
        for (int h = 1; h < HD; ++h) {
            const int base = OW3 + h * 8;
            const ulonglong2 wa = lds128(&w[base]);
            const u64        wc = lds64 (&w[base + 4]);
            #pragma unroll
            for (int t = 0; t < BT; ++t) {
                const u64 xp = bcast2(h2[t][h]);
                acc3[t][0] = fma2(xp, wa.x, acc3[t][0]);
                acc3[t][1] = fma2(xp, wa.y, acc3[t][1]);
                acc3[t][2] = fma2(xp, wc,   acc3[t][2]);
            }
        }

        // ---------------- packed 64-bit stores (4 x 192B contiguous regions) ----------
        #pragma unroll
        for (int t = 0; t < BT; ++t) {
            float* __restrict__ op = out + ((size_t)(b0 + t) * NNET + n) * LODD;
            *reinterpret_cast<u64*>(op)     = acc3[t][0];
            *reinterpret_cast<u64*>(op + 2) = acc3[t][1];
            *reinterpret_cast<u64*>(op + 4) = acc3[t][2];
        }
    }
}

extern "C" void kernel_launch(void* const* d_in, const int* in_sizes, int n_in,
                              void* d_out, int out_size)
{
    const float* prior  = (const float*)d_in[0];
    const float* camera = (const float*)d_in[1];
    const float* W1     = (const float*)d_in[2];
    const float* b1     = (const float*)d_in[3];
    const float* W2     = (const float*)d_in[4];
    const float* b2     = (const float*)d_in[5];
    const float* W3     = (const float*)d_in[6];
    const float* b3     = (const float*)d_in[7];
    float* out          = (float*)d_out;

    const int B = in_sizes[1] / CAMD;                       // 8192
    dim3 grid((NNET + NT - 1) / NT, B / BTILE);             // 91 x 8 = 728 CTAs
    grouped_mlp_kernel<<<grid, 256>>>(prior, camera, W1, b1, W2, b2, W3, b3, out);
}

// round 13
// speedup vs baseline: 1.0004x; 1.0004x over previous
#include <cuda_runtime.h>

#define NNET   722
#define CAMD   10
#define HD     10
#define LODD   6

#define NT     8       // networks per block; lane&7 -> network (4-way LDS broadcast)
#define WS     388     // floats per network; 388%32==4 -> 8 distinct 16B bank-slots; 16B-aligned
#define BT     4       // batch elements per thread
#define ITERS  8
#define BTILE  1024    // 8 warps * 4 groups * BT * ITERS

// padded smem layout per network (stride WS):
//   [0,132)    W1: 11 rows x 12 (10 used)
//   [132,144)  b1 (10 used)
//   [144,264)  W2: 10 rows x 12 (10 used)
//   [264,276)  b2 (10 used)
//   [276,356)  W3: 10 rows x 8 (6 used)
//   [356,364)  b3 (6 used)
#define OW1 0
#define OB1 132
#define OW2 144
#define OB2 264
#define OW3 276
#define OB3 356

typedef unsigned long long u64;

__device__ __forceinline__ u64 fma2(u64 a, u64 b, u64 c) {
    u64 d;
    asm("fma.rn.f32x2 %0, %1, %2, %3;" : "=l"(d) : "l"(a), "l"(b), "l"(c));
    return d;
}
__device__ __forceinline__ u64 bcast2(float x) {      // {x, x}
    u64 d;
    asm("mov.b64 %0, {%1, %1};" : "=l"(d) : "f"(x));
    return d;
}
__device__ __forceinline__ void unpack2(u64 v, float& lo, float& hi) {
    asm("mov.b64 {%0, %1}, %2;" : "=f"(lo), "=f"(hi) : "l"(v));
}
__device__ __forceinline__ u64 lds64(const float* p) {            // 1 pair
    return *reinterpret_cast<const u64*>(p);
}
__device__ __forceinline__ ulonglong2 lds128(const float* p) {    // 2 pairs
    return *reinterpret_cast<const ulonglong2*>(p);
}

__global__ __launch_bounds__(256, 2)
void grouped_mlp_kernel(const float* __restrict__ prior,
                        const float* __restrict__ camera,
                        const float* __restrict__ W1, const float* __restrict__ b1,
                        const float* __restrict__ W2, const float* __restrict__ b2,
                        const float* __restrict__ W3, const float* __restrict__ b3,
                        float* __restrict__ out)
{
    __shared__ __align__(16) float ws[NT * WS];

    const int tid    = threadIdx.x;
    const int n0     = blockIdx.x * NT;
    const int b_base = blockIdx.y * BTILE;

    // ---- cooperative weight staging into the padded layout ----
    for (int f = tid; f < NT * 110; f += 256) {
        int nl = f / 110, idx = f - nl * 110, i = idx / 10, c = idx - i * 10;
        if (n0 + nl < NNET) ws[nl * WS + OW1 + i * 12 + c] = W1[(n0 + nl) * 110 + idx];
    }
    for (int f = tid; f < NT * 10; f += 256) {
        int nl = f / 10, idx = f - nl * 10;
        if (n0 + nl < NNET) ws[nl * WS + OB1 + idx] = b1[(n0 + nl) * 10 + idx];
    }
    for (int f = tid; f < NT * 100; f += 256) {
        int nl = f / 100, idx = f - nl * 100, i = idx / 10, c = idx - i * 10;
        if (n0 + nl < NNET) ws[nl * WS + OW2 + i * 12 + c] = W2[(n0 + nl) * 100 + idx];
    }
    for (int f = tid; f < NT * 10; f += 256) {
        int nl = f / 10, idx = f - nl * 10;
        if (n0 + nl < NNET) ws[nl * WS + OB2 + idx] = b2[(n0 + nl) * 10 + idx];
    }
    for (int f = tid; f < NT * 60; f += 256) {
        int nl = f / 60, idx = f - nl * 60, h = idx / 6, c = idx - h * 6;
        if (n0 + nl < NNET) ws[nl * WS + OW3 + h * 8 + c] = W3[(n0 + nl) * 60 + idx];
    }
    for (int f = tid; f < NT * 6; f += 256) {
        int nl = f / 6, idx = f - nl * 6;
        if (n0 + nl < NNET) ws[nl * WS + OB3 + idx] = b3[(n0 + nl) * 6 + idx];
    }
    __syncthreads();

    const int nl = tid & 7;             // network (lanes nl, nl+8, nl+16, nl+24 share)
    const int g  = (tid >> 3) & 3;      // batch subgroup within warp
    const int wp = tid >> 5;            // warp id
    const int n  = n0 + nl;
    const float* __restrict__ w = &ws[nl * WS];

    if (n >= NNET) return;              // tail tile; no barriers below

    #pragma unroll 1
    for (int it = 0; it < ITERS; ++it) {
        const int b0 = b_base + it * 128 + wp * 16 + g * BT;

        // ---------------- layer 1: 11 -> 10 (h-pairs packed) ----------------
        u64 acc[BT][HD / 2];
        {   // feature 0 = prior (4 x 32B rows per warp, coalesced), bias folded
            const ulonglong2 wa = lds128(&w[OW1]);
            const ulonglong2 wb = lds128(&w[OW1 + 4]);
            const u64        wc = lds64 (&w[OW1 + 8]);
            const ulonglong2 ba = lds128(&w[OB1]);
            const ulonglong2 bb = lds128(&w[OB1 + 4]);
            const u64        bc = lds64 (&w[OB1 + 8]);
            #pragma unroll
            for (int t = 0; t < BT; ++t) {
                const u64 xp = bcast2(prior[(size_t)(b0 + t) * NNET + n]);
                acc[t][0] = fma2(xp, wa.x, ba.x);
                acc[t][1] = fma2(xp, wa.y, ba.y);
                acc[t][2] = fma2(xp, wb.x, bb.x);
                acc[t][3] = fma2(xp, wb.y, bb.y);
                acc[t][4] = fma2(xp, wc,   bc);
            }
        }
        #pragma unroll
        for (int m = 0; m < 5; ++m) {   // camera features in pairs (float2 LDG)
            float2 cv[BT];
            #pragma unroll
            for (int t = 0; t < BT; ++t)
                cv[t] = __ldg(reinterpret_cast<const float2*>(
                              camera + (size_t)(b0 + t) * CAMD + 2 * m));
            #pragma unroll
            for (int s = 0; s < 2; ++s) {
                const int base = OW1 + (2 * m + 1 + s) * 12;
                const ulonglong2 wa = lds128(&w[base]);
                const ulonglong2 wb = lds128(&w[base + 4]);
                const u64        wc = lds64 (&w[base + 8]);
                #pragma unroll
                for (int t = 0; t < BT; ++t) {
                    const u64 xp = bcast2(s ? cv[t].y : cv[t].x);
                    acc[t][0] = fma2(xp, wa.x, acc[t][0]);
                    acc[t][1] = fma2(xp, wa.y, acc[t][1]);
                    acc[t][2] = fma2(xp, wb.x, acc[t][2]);
                    acc[t][3] = fma2(xp, wb.y, acc[t][3]);
                    acc[t][4] = fma2(xp, wc,   acc[t][4]);
                }
            }
        }
        // relu -> h1 scalars
        float h1[BT][HD];
        #pragma unroll
        for (int t = 0; t < BT; ++t)
            #pragma unroll
            for (int j = 0; j < HD / 2; ++j) {
                float lo, hi; unpack2(acc[t][j], lo, hi);
                h1[t][2 * j]     = fmaxf(lo, 0.0f);
                h1[t][2 * j + 1] = fmaxf(hi, 0.0f);
            }

        // ---------------- layer 2: 10 -> 10 (k-pairs packed) ----------------
        u64 acc2[BT][HD / 2];
        {   // h = 0, bias folded
            const ulonglong2 wa = lds128(&w[OW2]);
            const ulonglong2 wb = lds128(&w[OW2 + 4]);
            const u64        wc = lds64 (&w[OW2 + 8]);
            const ulonglong2 ba = lds128(&w[OB2]);
            const ulonglong2 bb = lds128(&w[OB2 + 4]);
            const u64        bc = lds64 (&w[OB2 + 8]);
            #pragma unroll
            for (int t = 0; t < BT; ++t) {
                const u64 xp = bcast2(h1[t][0]);
                acc2[t][0] = fma2(xp, wa.x, ba.x);
                acc2[t][1] = fma2(xp, wa.y, ba.y);
                acc2[t][2] = fma2(xp, wb.x, bb.x);
                acc2[t][3] = fma2(xp, wb.y, bb.y);
                acc2[t][4] = fma2(xp, wc,   bc);
            }
        }
        #pragma unroll
        for (int h = 1; h < HD; ++h) {
            const int base = OW2 + h * 12;
            const ulonglong2 wa = lds128(&w[base]);
            const ulonglong2 wb = lds128(&w[base + 4]);
            const u64        wc = lds64 (&w[base + 8]);
            #pragma unroll
            for (int t = 0; t < BT; ++t) {
                const u64 xp = bcast2(h1[t][h]);
                acc2[t][0] = fma2(xp, wa.x, acc2[t][0]);
                acc2[t][1] = fma2(xp, wa.y, acc2[t][1]);
                acc2[t][2] = fma2(xp, wb.x, acc2[t][2]);
                acc2[t][3] = fma2(xp, wb.y, acc2[t][3]);
                acc2[t][4] = fma2(xp, wc,   acc2[t][4]);
            }
        }
        // relu -> h2 scalars
        float h2[BT][HD];
        #pragma unroll
        for (int t = 0; t < BT; ++t)
            #pragma unroll
            for (int j = 0; j < HD / 2; ++j) {
                float lo, hi; unpack2(acc2[t][j], lo, hi);
                h2[t][2 * j]     = fmaxf(lo, 0.0f);
                h2[t][2 * j + 1] = fmaxf(hi, 0.0f);
            }

        // ---------------- layer 3: 10 -> 6 (o-pairs packed) ----------------
        u64 acc3[BT][LODD / 2];
        {   // h = 0, bias folded
            const ulonglong2 wa = lds128(&w[OW3]);
            const u64        wc = lds64 (&w[OW3 + 4]);
            const ulonglong2 ba = lds128(&w[OB3]);
            const u64        bc = lds64 (&w[OB3 + 4]);
            #pragma unroll
            for (int t = 0; t < BT; ++t) {
                const u64 xp = bcast2(h2[t][0]);
                acc3[t][0] = fma2(xp, wa.x, ba.x);
                acc3[t][1] = fma2(xp, wa.y, ba.y);
                acc3[t][2] = fma2(xp, wc,   bc);
            }
        }
        #pragma unroll
        for (int h = 1; h < HD; ++h) {
            const int base = OW3 + h * 8;
            const ulonglong2 wa = lds128(&w[base]);
            const u64        wc = lds64 (&w[base + 4]);
            #pragma unroll
            for (int t = 0; t < BT; ++t) {
                const u64 xp = bcast2(h2[t][h]);
                acc3[t][0] = fma2(xp, wa.x, acc3[t][0]);
                acc3[t][1] = fma2(xp, wa.y, acc3[t][1]);
                acc3[t][2] = fma2(xp, wc,   acc3[t][2]);
            }
        }

        // ---------------- packed 64-bit stores (4 x 192B contiguous regions) ----------
        #pragma unroll
        for (int t = 0; t < BT; ++t) {
            float* __restrict__ op = out + ((size_t)(b0 + t) * NNET + n) * LODD;
            *reinterpret_cast<u64*>(op)     = acc3[t][0];
            *reinterpret_cast<u64*>(op + 2) = acc3[t][1];
            *reinterpret_cast<u64*>(op + 4) = acc3[t][2];
        }
    }
}

extern "C" void kernel_launch(void* const* d_in, const int* in_sizes, int n_in,
                              void* d_out, int out_size)
{
    const float* prior  = (const float*)d_in[0];
    const float* camera = (const float*)d_in[1];
    const float* W1     = (const float*)d_in[2];
    const float* b1     = (const float*)d_in[3];
    const float* W2     = (const float*)d_in[4];
    const float* b2     = (const float*)d_in[5];
    const float* W3     = (const float*)d_in[6];
    const float* b3     = (const float*)d_in[7];
    float* out          = (float*)d_out;

    const int B = in_sizes[1] / CAMD;                       // 8192
    dim3 grid((NNET + NT - 1) / NT, B / BTILE);             // 91 x 8 = 728 CTAs
    grouped_mlp_kernel<<<grid, 256>>>(prior, camera, W1, b1, W2, b2, W3, b3, out);
}